// round 1
// baseline (speedup 1.0000x reference)
#include <cuda_runtime.h>
#include <math.h>

// Problem constants
#define BB   4
#define SEQ  2048
#define DM   1024
#define DI   2048
#define MTOT (BB*SEQ)          // 8192 rows total
#define EPSV 1e-6f

// Scratch layout (single __device__ array; no runtime allocation allowed)
static constexpr size_t NQK     = (size_t)BB * SEQ * DI;   // 16,777,216 floats
static constexpr size_t OFF_Q   = 0;
static constexpr size_t OFF_K   = 1 * NQK;
static constexpr size_t OFF_V   = 2 * NQK;
static constexpr size_t OFF_S   = 3 * NQK;                 // SEQ==DI so same size
static constexpr size_t OFF_NUM = 4 * NQK;
static constexpr size_t OFF_DEN = 5 * NQK;                 // 8192 floats (1/den)
__device__ __align__(16) float g_scr[5 * NQK + (size_t)BB * SEQ];

__device__ __forceinline__ float phi_act(float v) {
    // elu(v)+1 : v>0 -> v+1 ; v<=0 -> exp(v)
    return v > 0.f ? v + 1.f : expf(v);
}

// ---------------------------------------------------------------------------
// Generic NN GEMM: C[M,N] = act(A[M,K] @ B[K,N] + bias[N]), optional per-row
// scale of A (rscale = g_scr[OFF_DEN + row], used for num/den in the output
// projection). 128x128x16 tiles, 256 threads, 8x8 per-thread microtile.
// All dims are multiples of tile sizes for this problem -> no bounds checks.
// ---------------------------------------------------------------------------
template<int ACT, bool SCALE, bool AEXT>
__global__ void __launch_bounds__(256) gemm_nn_kernel(
    const float* __restrict__ Aext, const float* __restrict__ B,
    const float* __restrict__ bias, float* __restrict__ Cext,
    size_t c_off, int M, int N, int K)
{
    const float* A = AEXT ? Aext : (g_scr + OFF_NUM);
    float* C = Cext ? Cext : (g_scr + c_off);

    __shared__ float As[16][128];
    __shared__ float Bs[16][128];

    const int tid  = threadIdx.x;
    const int row0 = blockIdx.y * 128;
    const int col0 = blockIdx.x * 128;
    const int ty = tid >> 4;
    const int tx = tid & 15;

    float acc[8][8];
#pragma unroll
    for (int i = 0; i < 8; i++)
#pragma unroll
        for (int j = 0; j < 8; j++) acc[i][j] = 0.f;

    for (int k0 = 0; k0 < K; k0 += 16) {
        // A tile: 128 rows x 16 k, stored transposed As[k][row]
#pragma unroll
        for (int s = 0; s < 2; s++) {
            int slot = tid + s * 256;
            int ar = slot >> 2;
            int ak = (slot & 3) << 2;
            float4 v = *(const float4*)(A + (size_t)(row0 + ar) * K + k0 + ak);
            if (SCALE) {
                float rs = g_scr[OFF_DEN + row0 + ar];
                v.x *= rs; v.y *= rs; v.z *= rs; v.w *= rs;
            }
            As[ak + 0][ar] = v.x; As[ak + 1][ar] = v.y;
            As[ak + 2][ar] = v.z; As[ak + 3][ar] = v.w;
        }
        // B tile: 16 k-rows x 128 cols, natural layout Bs[k][col]
#pragma unroll
        for (int s = 0; s < 2; s++) {
            int slot = tid + s * 256;
            int br = slot >> 5;
            int bc = (slot & 31) << 2;
            *(float4*)(&Bs[br][bc]) =
                *(const float4*)(B + (size_t)(k0 + br) * N + col0 + bc);
        }
        __syncthreads();
#pragma unroll
        for (int kk = 0; kk < 16; kk++) {
            float a[8], bv[8];
#pragma unroll
            for (int i = 0; i < 8; i++) a[i] = As[kk][ty * 8 + i];
#pragma unroll
            for (int j = 0; j < 8; j++) bv[j] = Bs[kk][tx * 8 + j];
#pragma unroll
            for (int i = 0; i < 8; i++)
#pragma unroll
                for (int j = 0; j < 8; j++)
                    acc[i][j] = fmaf(a[i], bv[j], acc[i][j]);
        }
        __syncthreads();
    }

    float bb[8];
#pragma unroll
    for (int j = 0; j < 8; j++) bb[j] = bias[col0 + tx * 8 + j];

#pragma unroll
    for (int i = 0; i < 8; i++) {
        size_t r = (size_t)(row0 + ty * 8 + i);
#pragma unroll
        for (int j = 0; j < 8; j += 4) {
            float4 o;
            o.x = acc[i][j + 0] + bb[j + 0];
            o.y = acc[i][j + 1] + bb[j + 1];
            o.z = acc[i][j + 2] + bb[j + 2];
            o.w = acc[i][j + 3] + bb[j + 3];
            if (ACT == 1) {
                o.x = phi_act(o.x); o.y = phi_act(o.y);
                o.z = phi_act(o.z); o.w = phi_act(o.w);
            }
            *(float4*)(C + r * N + col0 + tx * 8 + j) = o;
        }
    }
}

// ---------------------------------------------------------------------------
// Scores: S[b][n][m] = Q[b,n,:] . K[b,m,:] for m <= n (masked to 0 above the
// diagonal inside diagonal tiles). Only lower-triangular 128x128 tiles are
// launched: gridDim.x = 16*17/2 = 136 triangular tile indices, gridDim.y = B.
// ---------------------------------------------------------------------------
__global__ void __launch_bounds__(256) gemm_nt_scores_kernel()
{
    const int b = blockIdx.y;
    int t = blockIdx.x;
    int bn = (int)((sqrtf(8.f * t + 1.f) - 1.f) * 0.5f);
    while ((bn + 1) * (bn + 2) / 2 <= t) bn++;
    while (bn * (bn + 1) / 2 > t) bn--;
    const int bm = t - bn * (bn + 1) / 2;

    const float* A  = g_scr + OFF_Q + (size_t)b * SEQ * DI;  // [n, d]
    const float* Bm = g_scr + OFF_K + (size_t)b * SEQ * DI;  // [m, d]
    float* C        = g_scr + OFF_S + (size_t)b * SEQ * SEQ; // [n, m]

    __shared__ float As[16][128];
    __shared__ float Bs[16][128];

    const int tid  = threadIdx.x;
    const int row0 = bn * 128;     // n
    const int col0 = bm * 128;     // m
    const int ty = tid >> 4;
    const int tx = tid & 15;

    float acc[8][8];
#pragma unroll
    for (int i = 0; i < 8; i++)
#pragma unroll
        for (int j = 0; j < 8; j++) acc[i][j] = 0.f;

    for (int k0 = 0; k0 < DI; k0 += 16) {
#pragma unroll
        for (int s = 0; s < 2; s++) {
            int slot = tid + s * 256;
            int ar = slot >> 2;
            int ak = (slot & 3) << 2;
            float4 v = *(const float4*)(A + (size_t)(row0 + ar) * DI + k0 + ak);
            As[ak + 0][ar] = v.x; As[ak + 1][ar] = v.y;
            As[ak + 2][ar] = v.z; As[ak + 3][ar] = v.w;
        }
        // B is row-major [m, d]: load like A, store transposed Bs[k][m]
#pragma unroll
        for (int s = 0; s < 2; s++) {
            int slot = tid + s * 256;
            int br = slot >> 2;
            int bk = (slot & 3) << 2;
            float4 v = *(const float4*)(Bm + (size_t)(col0 + br) * DI + k0 + bk);
            Bs[bk + 0][br] = v.x; Bs[bk + 1][br] = v.y;
            Bs[bk + 2][br] = v.z; Bs[bk + 3][br] = v.w;
        }
        __syncthreads();
#pragma unroll
        for (int kk = 0; kk < 16; kk++) {
            float a[8], bv[8];
#pragma unroll
            for (int i = 0; i < 8; i++) a[i] = As[kk][ty * 8 + i];
#pragma unroll
            for (int j = 0; j < 8; j++) bv[j] = Bs[kk][tx * 8 + j];
#pragma unroll
            for (int i = 0; i < 8; i++)
#pragma unroll
                for (int j = 0; j < 8; j++)
                    acc[i][j] = fmaf(a[i], bv[j], acc[i][j]);
        }
        __syncthreads();
    }

    const bool diag = (bn == bm);
#pragma unroll
    for (int i = 0; i < 8; i++) {
        int n = row0 + ty * 8 + i;
#pragma unroll
        for (int j = 0; j < 8; j += 4) {
            int m = col0 + tx * 8 + j;
            float4 o;
            o.x = acc[i][j + 0]; o.y = acc[i][j + 1];
            o.z = acc[i][j + 2]; o.w = acc[i][j + 3];
            if (diag) {
                if (n < m + 0) o.x = 0.f;
                if (n < m + 1) o.y = 0.f;
                if (n < m + 2) o.z = 0.f;
                if (n < m + 3) o.w = 0.f;
            }
            *(float4*)(C + (size_t)n * SEQ + m) = o;
        }
    }
}

// ---------------------------------------------------------------------------
// Numerator: Num[b][n][e] = sum_{m<=n} S[b][n][m] * V[b][m][e].
// k-loop bounded at (bn+1)*128 (triangular skip). Blocks with blockIdx.x==0
// also accumulate row-sums of S (the denominator) while the S tile is in
// SMEM, and store 1/(den+eps).
// ---------------------------------------------------------------------------
__global__ void __launch_bounds__(256) gemm_num_kernel()
{
    const int b  = blockIdx.z;
    const int bn = blockIdx.y;   // row tile over n
    const int be = blockIdx.x;   // col tile over e

    const float* A  = g_scr + OFF_S + (size_t)b * SEQ * SEQ;  // [n, m]
    const float* Bm = g_scr + OFF_V + (size_t)b * SEQ * DI;   // [m, e]
    float* C        = g_scr + OFF_NUM + (size_t)b * SEQ * DI;

    __shared__ float As[16][128];
    __shared__ float Bs[16][128];

    const int tid  = threadIdx.x;
    const int row0 = bn * 128;
    const int col0 = be * 128;
    const int kmax = (bn + 1) * 128;
    const int ty = tid >> 4;
    const int tx = tid & 15;

    float acc[8][8];
#pragma unroll
    for (int i = 0; i < 8; i++)
#pragma unroll
        for (int j = 0; j < 8; j++) acc[i][j] = 0.f;
    float rsum = 0.f;

    for (int k0 = 0; k0 < kmax; k0 += 16) {
#pragma unroll
        for (int s = 0; s < 2; s++) {
            int slot = tid + s * 256;
            int ar = slot >> 2;
            int ak = (slot & 3) << 2;
            float4 v = *(const float4*)(A + (size_t)(row0 + ar) * SEQ + k0 + ak);
            As[ak + 0][ar] = v.x; As[ak + 1][ar] = v.y;
            As[ak + 2][ar] = v.z; As[ak + 3][ar] = v.w;
        }
#pragma unroll
        for (int s = 0; s < 2; s++) {
            int slot = tid + s * 256;
            int br = slot >> 5;
            int bc = (slot & 31) << 2;
            *(float4*)(&Bs[br][bc]) =
                *(const float4*)(Bm + (size_t)(k0 + br) * DI + col0 + bc);
        }
        __syncthreads();
        // Fused denominator: row-sums of the S tile (only e-tile 0 does it)
        if (be == 0 && tid < 128) {
            float s = 0.f;
#pragma unroll
            for (int kk = 0; kk < 16; kk++) s += As[kk][tid];
            rsum += s;
        }
#pragma unroll
        for (int kk = 0; kk < 16; kk++) {
            float a[8], bv[8];
#pragma unroll
            for (int i = 0; i < 8; i++) a[i] = As[kk][ty * 8 + i];
#pragma unroll
            for (int j = 0; j < 8; j++) bv[j] = Bs[kk][tx * 8 + j];
#pragma unroll
            for (int i = 0; i < 8; i++)
#pragma unroll
                for (int j = 0; j < 8; j++)
                    acc[i][j] = fmaf(a[i], bv[j], acc[i][j]);
        }
        __syncthreads();
    }

#pragma unroll
    for (int i = 0; i < 8; i++) {
        size_t r = (size_t)(row0 + ty * 8 + i);
#pragma unroll
        for (int j = 0; j < 8; j += 4) {
            float4 o;
            o.x = acc[i][j + 0]; o.y = acc[i][j + 1];
            o.z = acc[i][j + 2]; o.w = acc[i][j + 3];
            *(float4*)(C + r * DI + col0 + tx * 8 + j) = o;
        }
    }
    if (be == 0 && tid < 128) {
        g_scr[OFF_DEN + (size_t)b * SEQ + row0 + tid] = 1.f / (rsum + EPSV);
    }
}

// ---------------------------------------------------------------------------
extern "C" void kernel_launch(void* const* d_in, const int* in_sizes, int n_in,
                              void* d_out, int out_size)
{
    const float* x  = (const float*)d_in[0];
    const float* Wq = (const float*)d_in[1];
    const float* bq = (const float*)d_in[2];
    const float* Wk = (const float*)d_in[3];
    const float* bk = (const float*)d_in[4];
    const float* Wv = (const float*)d_in[5];
    const float* bv = (const float*)d_in[6];
    const float* Wo = (const float*)d_in[7];
    const float* bo = (const float*)d_in[8];
    float* out = (float*)d_out;

    dim3 blk(256);
    dim3 gridQKV(DI / 128, MTOT / 128);      // 16 x 64
    dim3 gridS(136, BB);                     // triangular tiles x batch
    dim3 gridN(DI / 128, SEQ / 128, BB);     // 16 x 16 x 4
    dim3 gridO(DM / 128, MTOT / 128);        // 8 x 64

    // Q = phi(x@Wq+bq), K = phi(x@Wk+bk), V = x@Wv+bv
    gemm_nn_kernel<1, false, true><<<gridQKV, blk>>>(x, Wq, bq, nullptr, OFF_Q, MTOT, DI, DM);
    gemm_nn_kernel<1, false, true><<<gridQKV, blk>>>(x, Wk, bk, nullptr, OFF_K, MTOT, DI, DM);
    gemm_nn_kernel<0, false, true><<<gridQKV, blk>>>(x, Wv, bv, nullptr, OFF_V, MTOT, DI, DM);

    // S = tril(Q K^T)  (lower-triangular tiles only)
    gemm_nt_scores_kernel<<<gridS, blk>>>();

    // Num = S @ V  (+ fused denominator row-sums -> 1/(den+eps))
    gemm_num_kernel<<<gridN, blk>>>();

    // out = (Num * deninv_row) @ Wo + bo
    gemm_nn_kernel<0, true, false><<<gridO, blk>>>(nullptr, Wo, bo, out, 0, MTOT, DM, DI);
}

// round 4
// speedup vs baseline: 3.1840x; 3.1840x over previous
#include <cuda_runtime.h>
#include <math.h>
#include <stdint.h>

#define BB   4
#define SEQ  2048
#define DM   1024
#define DI   2048
#define MTOT (BB*SEQ)
#define EPSV 1e-6f

// ---------------------------------------------------------------------------
// Scratch (static device array; no runtime allocation allowed)
// ---------------------------------------------------------------------------
static constexpr size_t NQK     = (size_t)BB * SEQ * DI;     // 16.78M floats
static constexpr size_t OFF_Q   = 0;
static constexpr size_t OFF_K   = 1 * NQK;
static constexpr size_t OFF_VT  = 2 * NQK;                   // V^T [e, m] per batch
static constexpr size_t OFF_S   = 3 * NQK;
static constexpr size_t OFF_NUM = 4 * NQK;
static constexpr size_t OFF_WQT = 5 * NQK;                   // Wq^T [2048,1024]
static constexpr size_t OFF_WKT = OFF_WQT + (size_t)DM * DI;
static constexpr size_t OFF_WVT = OFF_WKT + (size_t)DM * DI;
static constexpr size_t OFF_WOT = OFF_WVT + (size_t)DM * DI; // Wo^T [1024,2048]
static constexpr size_t OFF_DEN = OFF_WOT + (size_t)DM * DI; // 8192 floats (1/den)
__device__ __align__(1024) float g_scr[OFF_DEN + MTOT];

__device__ __forceinline__ uint32_t f2tf(float f) {
    uint32_t r;
    asm("cvt.rna.tf32.f32 %0, %1;" : "=r"(r) : "f"(f));
    return r;
}
__device__ __forceinline__ float phi_act(float v) {
    return v > 0.f ? v + 1.f : expf(v);
}

// ---------------------------------------------------------------------------
// tf32 mma.sync NT GEMM.  C[M,N] = A[M,K] @ B[N,K]^T  (both K-major).
// CTA tile 128x128, K-chunk 32, 256 threads = 8 warps (2 m x 4 n),
// warp tile 64x32 (4x4 m16n8k8 mma tiles, 4 k-steps of 8).
//
// SMEM staging is fragment-permuted: for every (mma-tile, k-step) the 32
// lanes' fragments are contiguous, so A frag = one LDS.128, B frag = one
// LDS.64. A blocks padded to 132 floats, B to 66, to stagger banks by ks.
//
// MODE: 0 plain | 1 col-bias+phi | 2 col-bias | 3 row-bias | 4 row-scale
//       | 5 causal mask on diagonal tile (with TRI decode of blockIdx.x).
// KLIM: k-loop bounded at (bn+1)*128 (numerator triangular skip).
// ---------------------------------------------------------------------------
static constexpr int STAGE_FLT = 32 * 132 + 64 * 66;     // 8448 floats
static constexpr int SMEM_BYTES = 2 * STAGE_FLT * 4;     // 67584 B

template<int MODE, bool TRI, bool KLIM>
__global__ void __launch_bounds__(256, 2) gemm_mma(
    const float* __restrict__ A, const float* __restrict__ B,
    float* __restrict__ C, int lda, int ldb, int ldc, int Ktot,
    size_t strA, size_t strB, size_t strC, const float* __restrict__ extra)
{
    extern __shared__ __align__(16) uint32_t smu[];
    const int tid  = threadIdx.x;
    const int wid  = tid >> 5;
    const int lane = tid & 31;
    const int wm   = wid & 1;        // warp row (0..1)  -> 64 rows each
    const int wn   = wid >> 1;       // warp col (0..3)  -> 32 cols each
    const int bz   = blockIdx.z;

    int bn, bm;
    if (TRI) {
        int t = blockIdx.x;
        bn = (int)((sqrtf(8.f * t + 1.f) - 1.f) * 0.5f);
        while ((bn + 1) * (bn + 2) / 2 <= t) bn++;
        while (bn * (bn + 1) / 2 > t) bn--;
        bm = t - bn * (bn + 1) / 2;
    } else { bn = blockIdx.y; bm = blockIdx.x; }
    const int row0 = bn * 128, col0 = bm * 128;

    A += (size_t)bz * strA;  B += (size_t)bz * strB;  C += (size_t)bz * strC;
    const float* aP = A + (size_t)row0 * lda;
    const float* bP = B + (size_t)col0 * ldb;

    const int kmax = KLIM ? (bn + 1) * 128 : Ktot;
    const int NC   = kmax >> 5;

    // Per-thread load geometry: 4 slots, each = one A float4 + one B float4.
    int lr[4], lk[4];
#pragma unroll
    for (int s = 0; s < 4; ++s) {
        int slot = s * 256 + tid;
        lr[s] = slot >> 3;            // row/col index 0..127
        lk[s] = (slot & 7) << 2;      // k offset 0,4,...,28
    }

    float acc[4][4][4];
#pragma unroll
    for (int i = 0; i < 4; i++)
#pragma unroll
        for (int j = 0; j < 4; j++)
#pragma unroll
            for (int q = 0; q < 4; q++) acc[i][j][q] = 0.f;

    float4 pa[4], pb[4];
#pragma unroll
    for (int s = 0; s < 4; ++s) {    // prefetch chunk 0
        pa[s] = *(const float4*)(aP + (size_t)lr[s] * lda + lk[s]);
        pb[s] = *(const float4*)(bP + (size_t)lr[s] * ldb + lk[s]);
    }

    // --- staging store (fragment-permuted, tf32-converted) ---
    auto stage_store = [&](int st) {
        uint32_t* sa = smu + st * STAGE_FLT;
        uint32_t* sbp = sa + 32 * 132;
#pragma unroll
        for (int s = 0; s < 4; ++s) {
            const int m = lr[s], kf = lk[s];
            const int ks = kf >> 3, hc = (kf >> 2) & 1;
            {   // A: element (m, kf+i) -> a-frag reg (r>>3)+2*hc, lane (r&7)*4+i
                const int mt = m >> 4, r = m & 15;
                uint32_t* p = sa + ((mt * 4 + ks) * 132) + (r & 7) * 16 + ((r >> 3) + 2 * hc);
                p[0]  = f2tf(pa[s].x); p[4]  = f2tf(pa[s].y);
                p[8]  = f2tf(pa[s].z); p[12] = f2tf(pa[s].w);
            }
            {   // B: element (n=m, kf+i) -> b-frag reg hc, lane (n&7)*4+i
                const int nt = m >> 3, ln = m & 7;
                uint32_t* p = sbp + ((nt * 4 + ks) * 66) + ln * 8 + hc;
                p[0] = f2tf(pb[s].x); p[2] = f2tf(pb[s].y);
                p[4] = f2tf(pb[s].z); p[6] = f2tf(pb[s].w);
            }
        }
    };

    stage_store(0);
    __syncthreads();

    for (int c = 0; c < NC; ++c) {
        if (c + 1 < NC) {            // prefetch next chunk (overlaps mma)
            const int k0 = (c + 1) << 5;
#pragma unroll
            for (int s = 0; s < 4; ++s) {
                pa[s] = *(const float4*)(aP + (size_t)lr[s] * lda + k0 + lk[s]);
                pb[s] = *(const float4*)(bP + (size_t)lr[s] * ldb + k0 + lk[s]);
            }
        }
        // compute on stage c&1
        const uint32_t* sa = smu + (c & 1) * STAGE_FLT;
        const uint32_t* sbp = sa + 32 * 132;
#pragma unroll
        for (int ks = 0; ks < 4; ++ks) {
            uint4 af[4];
            uint2 bf[4];
#pragma unroll
            for (int i = 0; i < 4; ++i)
                af[i] = *(const uint4*)(sa + (((wm * 4 + i) * 4 + ks) * 132) + lane * 4);
#pragma unroll
            for (int j = 0; j < 4; ++j)
                bf[j] = *(const uint2*)(sbp + (((wn * 4 + j) * 4 + ks) * 66) + lane * 2);
#pragma unroll
            for (int i = 0; i < 4; ++i)
#pragma unroll
                for (int j = 0; j < 4; ++j)
                    asm volatile(
                        "mma.sync.aligned.m16n8k8.row.col.f32.tf32.tf32.f32 "
                        "{%0,%1,%2,%3}, {%4,%5,%6,%7}, {%8,%9}, {%0,%1,%2,%3};"
                        : "+f"(acc[i][j][0]), "+f"(acc[i][j][1]),
                          "+f"(acc[i][j][2]), "+f"(acc[i][j][3])
                        : "r"(af[i].x), "r"(af[i].y), "r"(af[i].z), "r"(af[i].w),
                          "r"(bf[j].x), "r"(bf[j].y));
        }
        if (c + 1 < NC) {
            stage_store((c + 1) & 1);
        }
        __syncthreads();
    }

    // --- epilogue ---
    const int rbase = row0 + wm * 64 + (lane >> 2);
    const int cbase = col0 + wn * 32 + (lane & 3) * 2;
#pragma unroll
    for (int i = 0; i < 4; ++i) {
        const int r0 = rbase + i * 16;
        const int r1 = r0 + 8;
        float e0 = 0.f, e1 = 0.f;
        if (MODE == 3) { e0 = extra[r0]; e1 = extra[r1]; }
        if (MODE == 4) { e0 = extra[bz * SEQ + r0]; e1 = extra[bz * SEQ + r1]; }
#pragma unroll
        for (int j = 0; j < 4; ++j) {
            const int cc = cbase + j * 8;
            float v0 = acc[i][j][0], v1 = acc[i][j][1];
            float v2 = acc[i][j][2], v3 = acc[i][j][3];
            if (MODE == 1) {
                float b0 = extra[cc], b1 = extra[cc + 1];
                v0 = phi_act(v0 + b0); v1 = phi_act(v1 + b1);
                v2 = phi_act(v2 + b0); v3 = phi_act(v3 + b1);
            } else if (MODE == 2) {
                float b0 = extra[cc], b1 = extra[cc + 1];
                v0 += b0; v1 += b1; v2 += b0; v3 += b1;
            } else if (MODE == 3) {
                v0 += e0; v1 += e0; v2 += e1; v3 += e1;
            } else if (MODE == 4) {
                v0 *= e0; v1 *= e0; v2 *= e1; v3 *= e1;
            } else if (MODE == 5) {
                if (bn == bm) {
                    if (r0 < cc)     v0 = 0.f;
                    if (r0 < cc + 1) v1 = 0.f;
                    if (r1 < cc)     v2 = 0.f;
                    if (r1 < cc + 1) v3 = 0.f;
                }
            }
            *(float2*)(C + (size_t)r0 * ldc + cc) = make_float2(v0, v1);
            *(float2*)(C + (size_t)r1 * ldc + cc) = make_float2(v2, v3);
        }
    }
}

// ---------------------------------------------------------------------------
// Weight transpose: out[c][r] = in[r][c]
// ---------------------------------------------------------------------------
__global__ void transpose_k(const float* __restrict__ in, float* __restrict__ out,
                            int rows, int cols)
{
    __shared__ float t[32][33];
    int bx = blockIdx.x * 32, by = blockIdx.y * 32;
    int x = bx + threadIdx.x;
#pragma unroll
    for (int i = 0; i < 32; i += 8)
        t[threadIdx.y + i][threadIdx.x] = in[(size_t)(by + threadIdx.y + i) * cols + x];
    __syncthreads();
    int x2 = by + threadIdx.x;
#pragma unroll
    for (int i = 0; i < 32; i += 8)
        out[(size_t)(bx + threadIdx.y + i) * rows + x2] = t[threadIdx.x][threadIdx.y + i];
}

// ---------------------------------------------------------------------------
// Denominator: deninv[b*SEQ+n] = 1/(sum_{m<=n} S[b][n][m] + eps).
// One warp per row; upper part of the diagonal tile is already zero-masked.
// ---------------------------------------------------------------------------
__global__ void __launch_bounds__(256) denom_kernel()
{
    int warp = (blockIdx.x * blockDim.x + threadIdx.x) >> 5;
    int lane = threadIdx.x & 31;
    int b = warp >> 11;
    int n = warp & (SEQ - 1);
    const float* row = g_scr + OFF_S + (size_t)b * SEQ * SEQ + (size_t)n * SEQ;
    int mend = ((n >> 7) + 1) << 7;
    float s = 0.f;
    for (int m = lane * 4; m < mend; m += 128) {
        float4 v = *(const float4*)(row + m);
        s += v.x + v.y + v.z + v.w;
    }
#pragma unroll
    for (int o = 16; o; o >>= 1) s += __shfl_xor_sync(0xFFFFFFFFu, s, o);
    if (lane == 0) g_scr[OFF_DEN + warp] = 1.f / (s + EPSV);
}

// ---------------------------------------------------------------------------
extern "C" void kernel_launch(void* const* d_in, const int* in_sizes, int n_in,
                              void* d_out, int out_size)
{
    const float* x  = (const float*)d_in[0];
    const float* Wq = (const float*)d_in[1];
    const float* bq = (const float*)d_in[2];
    const float* Wk = (const float*)d_in[3];
    const float* bk = (const float*)d_in[4];
    const float* Wv = (const float*)d_in[5];
    const float* bv = (const float*)d_in[6];
    const float* Wo = (const float*)d_in[7];
    const float* bo = (const float*)d_in[8];
    float* out = (float*)d_out;

    float* scr = nullptr;
    cudaGetSymbolAddress((void**)&scr, g_scr);

    cudaFuncSetAttribute(gemm_mma<1, false, false>,
                         cudaFuncAttributeMaxDynamicSharedMemorySize, SMEM_BYTES);
    cudaFuncSetAttribute(gemm_mma<2, false, false>,
                         cudaFuncAttributeMaxDynamicSharedMemorySize, SMEM_BYTES);
    cudaFuncSetAttribute(gemm_mma<3, false, false>,
                         cudaFuncAttributeMaxDynamicSharedMemorySize, SMEM_BYTES);
    cudaFuncSetAttribute(gemm_mma<4, false, true>,
                         cudaFuncAttributeMaxDynamicSharedMemorySize, SMEM_BYTES);
    cudaFuncSetAttribute(gemm_mma<5, true, false>,
                         cudaFuncAttributeMaxDynamicSharedMemorySize, SMEM_BYTES);

    dim3 tb(32, 8);
    // Weight transposes: W[in,out] -> WT[out,in]
    transpose_k<<<dim3(DI / 32, DM / 32), tb>>>(Wq, scr + OFF_WQT, DM, DI);
    transpose_k<<<dim3(DI / 32, DM / 32), tb>>>(Wk, scr + OFF_WKT, DM, DI);
    transpose_k<<<dim3(DI / 32, DM / 32), tb>>>(Wv, scr + OFF_WVT, DM, DI);
    transpose_k<<<dim3(DM / 32, DI / 32), tb>>>(Wo, scr + OFF_WOT, DI, DM);

    // Q = phi(x @ Wq + bq)  [8192, 2048]
    gemm_mma<1, false, false><<<dim3(16, 64, 1), 256, SMEM_BYTES>>>(
        x, scr + OFF_WQT, scr + OFF_Q, DM, DM, DI, DM, 0, 0, 0, bq);
    // K = phi(x @ Wk + bk)
    gemm_mma<1, false, false><<<dim3(16, 64, 1), 256, SMEM_BYTES>>>(
        x, scr + OFF_WKT, scr + OFF_K, DM, DM, DI, DM, 0, 0, 0, bk);
    // Vt[e, m] = (x @ Wv + bv)^T per batch  [2048e, 2048m]
    gemm_mma<3, false, false><<<dim3(16, 16, BB), 256, SMEM_BYTES>>>(
        scr + OFF_WVT, x, scr + OFF_VT, DM, DM, SEQ, DM,
        0, (size_t)SEQ * DM, (size_t)SEQ * DI, bv);
    // S = tril(Q K^T) per batch (triangular tiles only, diagonal masked)
    gemm_mma<5, true, false><<<dim3(136, 1, BB), 256, SMEM_BYTES>>>(
        scr + OFF_Q, scr + OFF_K, scr + OFF_S, DI, DI, SEQ, DI,
        (size_t)SEQ * DI, (size_t)SEQ * DI, (size_t)SEQ * SEQ, nullptr);
    // deninv = 1/(rowsum(S) + eps)
    denom_kernel<<<MTOT / 8, 256>>>();
    // Num[n, e] = (sum_{m<=n} S[n,m] Vt[e,m]) * deninv[n]
    gemm_mma<4, false, true><<<dim3(16, 16, BB), 256, SMEM_BYTES>>>(
        scr + OFF_S, scr + OFF_VT, scr + OFF_NUM, SEQ, SEQ, DI, SEQ,
        (size_t)SEQ * SEQ, (size_t)SEQ * DI, (size_t)SEQ * DI, scr + OFF_DEN);
    // out = Num @ Wo + bo  [8192, 1024]
    gemm_mma<2, false, false><<<dim3(8, 64, 1), 256, SMEM_BYTES>>>(
        scr + OFF_NUM, scr + OFF_WOT, out, DI, DI, DM, DI, 0, 0, 0, bo);
}

// round 7
// speedup vs baseline: 5.2364x; 1.6446x over previous
#include <cuda_runtime.h>
#include <cuda_fp16.h>
#include <math.h>
#include <stdint.h>

#define BB   4
#define SEQ  2048
#define DM   1024
#define DI   2048
#define MTOT (BB*SEQ)
#define EPSV 1e-6f

// ---------------------------------------------------------------------------
// Scratch (static device arrays; no runtime allocation allowed).
// All big intermediates are fp16.
// ---------------------------------------------------------------------------
static constexpr size_t NQK   = (size_t)BB * SEQ * DI;       // 16.78M elems
static constexpr size_t HQ    = 0;
static constexpr size_t HK    = 1 * NQK;
static constexpr size_t HVT   = 2 * NQK;                     // V^T [e, m] per batch
static constexpr size_t HS    = 3 * NQK;
static constexpr size_t HNUM  = 4 * NQK;                     // (Num * deninv), O(1)
static constexpr size_t HWQT  = 5 * NQK;                     // Wq^T [2048,1024]
static constexpr size_t HWKT  = HWQT + (size_t)DM * DI;
static constexpr size_t HWVT  = HWKT + (size_t)DM * DI;
static constexpr size_t HWOT  = HWVT + (size_t)DM * DI;      // Wo^T [1024,2048]
static constexpr size_t HX    = HWOT + (size_t)DM * DI;      // x as fp16 [8192,1024]
static constexpr size_t HTOT  = HX + (size_t)MTOT * DM;
__device__ __align__(1024) __half g_h[HTOT];
__device__ __align__(16)   float  g_den[MTOT];               // 1/(den+eps)

__device__ __forceinline__ uint32_t h2u(__half2 h) {
    return *reinterpret_cast<uint32_t*>(&h);
}
__device__ __forceinline__ float phi_act(float v) {
    return v > 0.f ? v + 1.f : expf(v);
}

// ---------------------------------------------------------------------------
// x (fp32) -> fp16, vectorized
// ---------------------------------------------------------------------------
__global__ void __launch_bounds__(256) cvt_x_kernel(const float* __restrict__ x)
{
    size_t i = ((size_t)blockIdx.x * 256 + threadIdx.x) * 8;
    float4 a = *(const float4*)(x + i);
    float4 b = *(const float4*)(x + i + 4);
    uint4 o;
    o.x = h2u(__floats2half2_rn(a.x, a.y));
    o.y = h2u(__floats2half2_rn(a.z, a.w));
    o.z = h2u(__floats2half2_rn(b.x, b.y));
    o.w = h2u(__floats2half2_rn(b.z, b.w));
    *(uint4*)(g_h + HX + i) = o;
}

// ---------------------------------------------------------------------------
// fp16 mma.sync NT GEMM.  C[M,N] = A[M,K] @ B[N,K]^T  (both K-major fp16).
// CTA tile 128x128, K-chunk 32, 256 threads = 8 warps (2m x 4n),
// warp tile 64x32 = 4x4 m16n8k16 mma tiles, 2 k-steps of 16 per chunk.
//
// SMEM staging is fragment-permuted: per (mma-tile, k-step) the 32 lanes'
// fragments are contiguous -> A frag = one LDS.128, B frag = one LDS.64.
//
// MODE: 0 plain | 1 col-bias+phi | 2 col-bias | 3 row-bias | 4 row-scale
//       | 5 causal mask on diagonal tile. TRI: triangular blockIdx.x decode.
// KLIM: k-loop bounded at (bn+1)*128. HOUT: fp16 C (else fp32 C).
// ---------------------------------------------------------------------------
static constexpr int A_BLK = 132;                 // 128 u32 + pad
static constexpr int B_BLK = 66;                  // 64 u32 + pad
static constexpr int STAGE_U32 = 16 * A_BLK + 32 * B_BLK;   // 4224
static constexpr int SMEM_BYTES = 2 * STAGE_U32 * 4;        // 33792 B

template<int MODE, bool TRI, bool KLIM, bool HOUT>
__global__ void __launch_bounds__(256, 2) gemm_mma(
    const __half* __restrict__ A, const __half* __restrict__ B,
    void* __restrict__ Cv, int lda, int ldb, int ldc, int Ktot,
    size_t strA, size_t strB, size_t strC, const float* __restrict__ extra)
{
    extern __shared__ __align__(16) uint32_t smu[];
    const int tid  = threadIdx.x;
    const int wid  = tid >> 5;
    const int lane = tid & 31;
    const int wm   = wid & 1;
    const int wn   = wid >> 1;
    const int bz   = blockIdx.z;

    int bn, bm;
    if (TRI) {
        int t = blockIdx.x;
        bn = (int)((sqrtf(8.f * t + 1.f) - 1.f) * 0.5f);
        while ((bn + 1) * (bn + 2) / 2 <= t) bn++;
        while (bn * (bn + 1) / 2 > t) bn--;
        bm = t - bn * (bn + 1) / 2;
    } else { bn = blockIdx.y; bm = blockIdx.x; }
    const int row0 = bn * 128, col0 = bm * 128;

    const __half* aP = A + (size_t)bz * strA + (size_t)row0 * lda;
    const __half* bP = B + (size_t)bz * strB + (size_t)col0 * ldb;

    const int kmax = KLIM ? (bn + 1) * 128 : Ktot;
    const int NC   = kmax >> 5;

    // load geometry: 2 slots per thread per operand; each slot = one uint4
    // (8 halfs along k).  slot -> row 0..127, k-offset {0,8,16,24}.
    int ar[2], ak[2];
#pragma unroll
    for (int s = 0; s < 2; ++s) {
        int slot = s * 256 + tid;
        ar[s] = slot >> 2;
        ak[s] = (slot & 3) << 3;
    }

    uint4 pa[2], pb[2];
    auto load_chunk = [&](int k0) {
#pragma unroll
        for (int s = 0; s < 2; ++s) {
            pa[s] = *(const uint4*)(aP + (size_t)ar[s] * lda + k0 + ak[s]);
            pb[s] = *(const uint4*)(bP + (size_t)ar[s] * ldb + k0 + ak[s]);
        }
    };

    // Fragment-permuted scatter.  For element (r, kk) of a 16x16 A tile:
    // reg=(r>>3)+2*(kk>>3), lane=(r&7)*4+((kk&7)>>1).  Our uint4 covers
    // kk0..kk0+7 with kk0 in {0,8} of k-step ks, so the 4 u32s land at
    // lanes (r&7)*4 + 0..3, fixed reg.  B: reg=kk>>3, lane=(n&7)*4+j.
    auto stage_store = [&](int st) {
        uint32_t* sa = smu + st * STAGE_U32;
        uint32_t* sb = sa + 16 * A_BLK;
#pragma unroll
        for (int s = 0; s < 2; ++s) {
            const int r = ar[s] & 15, mt = ar[s] >> 4;
            const int ks = ak[s] >> 4, kk0 = ak[s] & 15;
            {
                const int reg = (r >> 3) + 2 * (kk0 >> 3);
                const int lb = (r & 7) * 4;
                uint32_t* p = sa + (mt * 2 + ks) * A_BLK + reg;
                p[(lb + 0) * 4] = pa[s].x; p[(lb + 1) * 4] = pa[s].y;
                p[(lb + 2) * 4] = pa[s].z; p[(lb + 3) * 4] = pa[s].w;
            }
            {
                const int n = ar[s], nt = n >> 3;
                const int reg = kk0 >> 3;
                const int lb = (n & 7) * 4;
                uint32_t* p = sb + (nt * 2 + ks) * B_BLK + reg;
                p[(lb + 0) * 2] = pb[s].x; p[(lb + 1) * 2] = pb[s].y;
                p[(lb + 2) * 2] = pb[s].z; p[(lb + 3) * 2] = pb[s].w;
            }
        }
    };

    float acc[4][4][4];
#pragma unroll
    for (int i = 0; i < 4; i++)
#pragma unroll
        for (int j = 0; j < 4; j++)
#pragma unroll
            for (int q = 0; q < 4; q++) acc[i][j][q] = 0.f;

    load_chunk(0);
    stage_store(0);
    __syncthreads();

    for (int c = 0; c < NC; ++c) {
        if (c + 1 < NC) load_chunk((c + 1) << 5);
        const uint32_t* sa = smu + (c & 1) * STAGE_U32;
        const uint32_t* sb = sa + 16 * A_BLK;
#pragma unroll
        for (int ks = 0; ks < 2; ++ks) {
            uint4 af[4];
            uint2 bf[4];
#pragma unroll
            for (int i = 0; i < 4; ++i)
                af[i] = *(const uint4*)(sa + (((wm * 4 + i) * 2 + ks) * A_BLK) + lane * 4);
#pragma unroll
            for (int j = 0; j < 4; ++j)
                bf[j] = *(const uint2*)(sb + (((wn * 4 + j) * 2 + ks) * B_BLK) + lane * 2);
#pragma unroll
            for (int i = 0; i < 4; ++i)
#pragma unroll
                for (int j = 0; j < 4; ++j)
                    asm volatile(
                        "mma.sync.aligned.m16n8k16.row.col.f32.f16.f16.f32 "
                        "{%0,%1,%2,%3}, {%4,%5,%6,%7}, {%8,%9}, {%0,%1,%2,%3};"
                        : "+f"(acc[i][j][0]), "+f"(acc[i][j][1]),
                          "+f"(acc[i][j][2]), "+f"(acc[i][j][3])
                        : "r"(af[i].x), "r"(af[i].y), "r"(af[i].z), "r"(af[i].w),
                          "r"(bf[j].x), "r"(bf[j].y));
        }
        if (c + 1 < NC) stage_store((c + 1) & 1);
        __syncthreads();
    }

    // --- epilogue ---
    const int rbase = row0 + wm * 64 + (lane >> 2);
    const int cbase = col0 + wn * 32 + (lane & 3) * 2;
#pragma unroll
    for (int i = 0; i < 4; ++i) {
        const int r0 = rbase + i * 16;
        const int r1 = r0 + 8;
        float e0 = 0.f, e1 = 0.f;
        if (MODE == 3) { e0 = extra[r0]; e1 = extra[r1]; }
        if (MODE == 4) { e0 = extra[bz * SEQ + r0]; e1 = extra[bz * SEQ + r1]; }
#pragma unroll
        for (int j = 0; j < 4; ++j) {
            const int cc = cbase + j * 8;
            float v0 = acc[i][j][0], v1 = acc[i][j][1];
            float v2 = acc[i][j][2], v3 = acc[i][j][3];
            if (MODE == 1) {
                float b0 = extra[cc], b1 = extra[cc + 1];
                v0 = phi_act(v0 + b0); v1 = phi_act(v1 + b1);
                v2 = phi_act(v2 + b0); v3 = phi_act(v3 + b1);
            } else if (MODE == 2) {
                float b0 = extra[cc], b1 = extra[cc + 1];
                v0 += b0; v1 += b1; v2 += b0; v3 += b1;
            } else if (MODE == 3) {
                v0 += e0; v1 += e0; v2 += e1; v3 += e1;
            } else if (MODE == 4) {
                v0 *= e0; v1 *= e0; v2 *= e1; v3 *= e1;
            } else if (MODE == 5) {
                if (bn == bm) {
                    if (r0 < cc)     v0 = 0.f;
                    if (r0 < cc + 1) v1 = 0.f;
                    if (r1 < cc)     v2 = 0.f;
                    if (r1 < cc + 1) v3 = 0.f;
                }
            }
            if (HOUT) {
                __half* cp = (__half*)Cv + (size_t)bz * strC;
                *(__half2*)(cp + (size_t)r0 * ldc + cc) = __floats2half2_rn(v0, v1);
                *(__half2*)(cp + (size_t)r1 * ldc + cc) = __floats2half2_rn(v2, v3);
            } else {
                float* cp = (float*)Cv + (size_t)bz * strC;
                *(float2*)(cp + (size_t)r0 * ldc + cc) = make_float2(v0, v1);
                *(float2*)(cp + (size_t)r1 * ldc + cc) = make_float2(v2, v3);
            }
        }
    }
}

// ---------------------------------------------------------------------------
// Weight transpose to fp16: out[c][r] = (half)in[r][c]
// ---------------------------------------------------------------------------
__global__ void transpose_k(const float* __restrict__ in, __half* __restrict__ out,
                            int rows, int cols)
{
    __shared__ float t[32][33];
    int bx = blockIdx.x * 32, by = blockIdx.y * 32;
    int x = bx + threadIdx.x;
#pragma unroll
    for (int i = 0; i < 32; i += 8)
        t[threadIdx.y + i][threadIdx.x] = in[(size_t)(by + threadIdx.y + i) * cols + x];
    __syncthreads();
    int x2 = by + threadIdx.x;
#pragma unroll
    for (int i = 0; i < 32; i += 8)
        out[(size_t)(bx + threadIdx.y + i) * rows + x2] =
            __float2half(t[threadIdx.x][threadIdx.y + i]);
}

// ---------------------------------------------------------------------------
// Denominator: deninv[b*SEQ+n] = 1/(sum_{m<=n} S[n,m] + eps).  S is fp16.
// One warp per row; upper part of the diagonal tile is already zero-masked,
// tiles above the diagonal are never touched (mend guard).
// ---------------------------------------------------------------------------
__global__ void __launch_bounds__(256) denom_kernel()
{
    int warp = (blockIdx.x * blockDim.x + threadIdx.x) >> 5;
    int lane = threadIdx.x & 31;
    int b = warp >> 11;
    int n = warp & (SEQ - 1);
    const __half* row = g_h + HS + (size_t)b * SEQ * SEQ + (size_t)n * SEQ;
    int mend = ((n >> 7) + 1) << 7;
    float s = 0.f;
    for (int m = lane * 8; m < mend; m += 256) {
        uint4 v = *(const uint4*)(row + m);
        const __half2* h = (const __half2*)&v;
#pragma unroll
        for (int i = 0; i < 4; ++i) {
            float2 f = __half22float2(h[i]);
            s += f.x + f.y;
        }
    }
#pragma unroll
    for (int o = 16; o; o >>= 1) s += __shfl_xor_sync(0xFFFFFFFFu, s, o);
    if (lane == 0) g_den[warp] = 1.f / (s + EPSV);
}

// ---------------------------------------------------------------------------
extern "C" void kernel_launch(void* const* d_in, const int* in_sizes, int n_in,
                              void* d_out, int out_size)
{
    const float* x  = (const float*)d_in[0];
    const float* Wq = (const float*)d_in[1];
    const float* bq = (const float*)d_in[2];
    const float* Wk = (const float*)d_in[3];
    const float* bk = (const float*)d_in[4];
    const float* Wv = (const float*)d_in[5];
    const float* bv = (const float*)d_in[6];
    const float* Wo = (const float*)d_in[7];
    const float* bo = (const float*)d_in[8];
    float* out = (float*)d_out;

    __half* h = nullptr;
    cudaGetSymbolAddress((void**)&h, g_h);
    float* den = nullptr;
    cudaGetSymbolAddress((void**)&den, g_den);

    dim3 tb(32, 8);
    // x -> fp16
    cvt_x_kernel<<<(MTOT * DM) / (256 * 8), 256>>>(x);
    // Weight transposes: W[in,out] -> WT[out,in] (fp16)
    transpose_k<<<dim3(DI / 32, DM / 32), tb>>>(Wq, h + HWQT, DM, DI);
    transpose_k<<<dim3(DI / 32, DM / 32), tb>>>(Wk, h + HWKT, DM, DI);
    transpose_k<<<dim3(DI / 32, DM / 32), tb>>>(Wv, h + HWVT, DM, DI);
    transpose_k<<<dim3(DM / 32, DI / 32), tb>>>(Wo, h + HWOT, DI, DM);

    // Q = phi(xh @ WqT^T + bq)  [8192, 2048] fp16
    gemm_mma<1, false, false, true><<<dim3(16, 64, 1), 256, SMEM_BYTES>>>(
        h + HX, h + HWQT, h + HQ, DM, DM, DI, DM, 0, 0, 0, bq);
    // K = phi(xh @ WkT^T + bk)
    gemm_mma<1, false, false, true><<<dim3(16, 64, 1), 256, SMEM_BYTES>>>(
        h + HX, h + HWKT, h + HK, DM, DM, DI, DM, 0, 0, 0, bk);
    // Vt[e, m] = (xh @ Wv + bv)^T per batch  [2048e, 2048m] fp16
    gemm_mma<3, false, false, true><<<dim3(16, 16, BB), 256, SMEM_BYTES>>>(
        h + HWVT, h + HX, h + HVT, DM, DM, SEQ, DM,
        0, (size_t)SEQ * DM, (size_t)DI * SEQ, bv);
    // S = tril(Q K^T) per batch (triangular tiles only, diagonal masked) fp16
    gemm_mma<5, true, false, true><<<dim3(136, 1, BB), 256, SMEM_BYTES>>>(
        h + HQ, h + HK, h + HS, DI, DI, SEQ, DI,
        (size_t)SEQ * DI, (size_t)SEQ * DI, (size_t)SEQ * SEQ, nullptr);
    // deninv = 1/(rowsum(S) + eps)
    denom_kernel<<<MTOT / 8, 256>>>();
    // Num[n, e] = (sum_{m<=n} S[n,m] Vt[e,m]) * deninv[n]  fp16 (O(1) values)
    gemm_mma<4, false, true, true><<<dim3(16, 16, BB), 256, SMEM_BYTES>>>(
        h + HS, h + HVT, h + HNUM, SEQ, SEQ, DI, SEQ,
        (size_t)SEQ * SEQ, (size_t)DI * SEQ, (size_t)SEQ * DI, den);
    // out = Num @ WoT^T + bo  [8192, 1024] fp32
    gemm_mma<2, false, false, false><<<dim3(8, 64, 1), 256, SMEM_BYTES>>>(
        h + HNUM, h + HWOT, out, DI, DI, DM, DI, 0, 0, 0, bo);
}